// round 12
// baseline (speedup 1.0000x reference)
#include <cuda_runtime.h>
#include <cuda_fp16.h>
#include <cstdint>

#define NN 100000
#define EE 600000
#define DD 128
#define GB 98            // k_deg grid (all blocks resident: 98 <= 148 SMs)
#define GT 1024          // k_deg block
#define SX 136           // smem row stride in words

// ---- device scratch (allocation-free rule: __device__ globals) ----
__device__ __align__(16) uint32_t g_h1h[(size_t)NN * 64]; // (x@W1)*dinv, fp16x2
__device__ __align__(16) float2 g_h2w[NN];               // layer-2 lin out * dinv
__device__ __align__(16) uint32_t g_w16[64 * DD];        // W1 packed half2 [k2][n]
__device__ int   g_cnt[NN];      // zeroed at end of each pass (k_deg phase2)
__device__ int   g_cur[NN];      // zeroed by k_agg1 each pass
__device__ int   g_off[NN + 1];
__device__ int   g_bsum[GB];
__device__ int   g_csr[EE];
__device__ float g_dinv[NN];
__device__ int   g_ctr[2];       // grid barriers; zeroed by k_agg1 each pass
__device__ int   g_is64;

// ---------------- grid barrier (all GB blocks resident) ----------------
__device__ __forceinline__ void gsync(int idx, int nb) {
    __syncthreads();
    if (threadIdx.x == 0) {
        __threadfence();
        atomicAdd(&g_ctr[idx], 1);
        while (((volatile int*)g_ctr)[idx] < nb) { }
        __threadfence();
    }
    __syncthreads();
}

// ============ k_deg: detect + count + wpack + scan + dinv ============
__global__ void __launch_bounds__(GT) k_deg(const void* __restrict__ ei,
                                            const float* __restrict__ W1,
                                            int n, int e, int nb) {
    __shared__ int s_is64;
    __shared__ int wsum[32];
    __shared__ int s_pre;
    int tid = threadIdx.x, lane = tid & 31, wid = tid >> 5;
    int b = blockIdx.x;
    int gstep = nb * GT;
    int gtid = b * GT + tid;

    if (tid == 0) {
        const unsigned* w = (const unsigned*)ei;
        int all0 = 1;
        for (int j = 1; j < 128; j += 2) all0 &= (w[j] == 0u);
        s_is64 = all0;
        if (b == 0) g_is64 = all0;
    }
    __syncthreads();
    int is64 = s_is64;

    // ---- phase0: degree count + W1 fp16 pack [k2][n] ----
    for (int i = gtid; i < e; i += gstep) {
        int t = is64 ? (int)((const long long*)ei)[(long long)e + i]
                     : ((const int*)ei)[e + i];
        if ((unsigned)t < (unsigned)n) atomicAdd(&g_cnt[t], 1);
    }
    for (int i = gtid; i < 64 * DD; i += gstep) {
        int k2 = i >> 7, nn = i & 127;
        __half2 p = __floats2half2_rn(W1[(2 * k2) * DD + nn],
                                      W1[(2 * k2 + 1) * DD + nn]);
        g_w16[i] = *(uint32_t*)&p;
    }
    gsync(0, nb);

    // ---- phase1: per-block exclusive scan of its 1024-count segment ----
    int i = b * GT + tid;
    int v = (i < n) ? g_cnt[i] : 0;
    int incl = v;
#pragma unroll
    for (int d = 1; d < 32; d <<= 1) {
        int y = __shfl_up_sync(0xffffffffu, incl, d);
        if (lane >= d) incl += y;
    }
    if (lane == 31) wsum[wid] = incl;
    __syncthreads();
    if (wid == 0) {
        int s = wsum[lane];
#pragma unroll
        for (int d = 1; d < 32; d <<= 1) {
            int y = __shfl_up_sync(0xffffffffu, s, d);
            if (lane >= d) s += y;
        }
        wsum[lane] = s;
    }
    __syncthreads();
    int wprev = wid ? wsum[wid - 1] : 0;
    int excl = wprev + incl - v;
    if (i < n) g_off[i] = excl;
    if (tid == GT - 1) g_bsum[b] = wprev + incl;
    gsync(1, nb);

    // ---- phase2: propagate block prefix; dinv; zero g_cnt for replay ----
    if (tid == 0) {
        int p = 0;
        for (int j = 0; j < b; j++) p += g_bsum[j];
        s_pre = p;
        if (b == nb - 1) g_off[n] = p + g_bsum[b];
    }
    __syncthreads();
    if (i < n) {
        g_off[i] += s_pre;
        g_dinv[i] = rsqrtf((float)(g_cnt[i] + 1));   // +1 = self-loop
        g_cnt[i] = 0;
    }
}

// ---------------- k_fill: CSR fill (runs concurrent with GEMM) ----------------
__global__ void k_fill(const void* __restrict__ ei, int e, int n) {
    int i = blockIdx.x * blockDim.x + threadIdx.x;
    if (i >= e) return;
    int is64 = g_is64;
    int t = is64 ? (int)((const long long*)ei)[(long long)e + i]
                 : ((const int*)ei)[e + i];
    int s = is64 ? (int)((const long long*)ei)[i]
                 : ((const int*)ei)[i];
    if ((unsigned)t < (unsigned)n && (unsigned)s < (unsigned)n) {
        int p = atomicAdd(&g_cur[t], 1);
        g_csr[g_off[t] + p] = s;
    }
}

// ---------------- fp16 mma ----------------
__device__ __forceinline__ void mma16(float* c, const uint32_t* a, const uint32_t* b) {
    asm volatile(
        "mma.sync.aligned.m16n8k16.row.col.f32.f16.f16.f32 "
        "{%0,%1,%2,%3},{%4,%5,%6,%7},{%8,%9},{%0,%1,%2,%3};"
        : "+f"(c[0]), "+f"(c[1]), "+f"(c[2]), "+f"(c[3])
        : "r"(a[0]), "r"(a[1]), "r"(a[2]), "r"(a[3]), "r"(b[0]), "r"(b[1]));
}

// ------- GEMM1: fp16 MMA, fp32 accum; epilogue scales row by dinv[row] -------
__global__ void __launch_bounds__(256, 2)
k_gemm1_tc(const float* __restrict__ x, int n) {
    __shared__ uint32_t Xs[32 * SX];
    __shared__ uint32_t Ws[32 * SX];
    int tid = threadIdx.x;
    int wid = tid >> 5, lane = tid & 31;
    int gid = lane >> 2, tig = lane & 3;
    int warpM = wid & 3;
    int warpN = wid >> 2;
    int row0 = blockIdx.x * 128;

    float acc[2][8][4];
#pragma unroll
    for (int mt = 0; mt < 2; mt++)
#pragma unroll
        for (int nt = 0; nt < 8; nt++)
#pragma unroll
            for (int j = 0; j < 4; j++) acc[mt][nt][j] = 0.f;

    for (int c = 0; c < 2; c++) {
#pragma unroll
        for (int j = 0; j < 8; j++) {
            int idx = tid + j * 256;
            int r = idx >> 4, q = idx & 15;
            float4 v = make_float4(0.f, 0.f, 0.f, 0.f);
            if (row0 + r < n)
                v = *(const float4*)(x + (size_t)(row0 + r) * DD + c * 64 + q * 4);
            __half2 p0 = __floats2half2_rn(v.x, v.y);
            __half2 p1 = __floats2half2_rn(v.z, v.w);
            int rs = r ^ q;
            Xs[(2 * q) * SX + rs]     = *(uint32_t*)&p0;
            Xs[(2 * q + 1) * SX + rs] = *(uint32_t*)&p1;
        }
#pragma unroll
        for (int j = 0; j < 16; j++) {
            int idx = tid + j * 256;
            int k2 = idx >> 7, nn = idx & 127;
            uint32_t w = g_w16[(size_t)(c * 32 + k2) * DD + nn];
            Ws[k2 * SX + (nn ^ ((k2 >> 1) & 31))] = w;
        }
        __syncthreads();

#pragma unroll
        for (int ks = 0; ks < 4; ks++) {
            int m0 = ks * 4 + (tig >> 1);
            int m1 = m0 + 2;
            int k2a = ks * 8 + tig, k2b = k2a + 4;
            uint32_t a[2][4];
#pragma unroll
            for (int mt = 0; mt < 2; mt++) {
                int rb = warpM * 32 + mt * 16 + gid;
                a[mt][0] = Xs[k2a * SX + (rb ^ m0)];
                a[mt][1] = Xs[k2a * SX + ((rb + 8) ^ m0)];
                a[mt][2] = Xs[k2b * SX + (rb ^ m1)];
                a[mt][3] = Xs[k2b * SX + ((rb + 8) ^ m1)];
            }
#pragma unroll
            for (int nt = 0; nt < 8; nt++) {
                int nb = warpN * 64 + nt * 8 + gid;
                uint32_t b[2];
                b[0] = Ws[k2a * SX + (nb ^ m0)];
                b[1] = Ws[k2b * SX + (nb ^ m1)];
#pragma unroll
                for (int mt = 0; mt < 2; mt++)
                    mma16(acc[mt][nt], a[mt], b);
            }
        }
        __syncthreads();
    }

    // epilogue: scale by dinv[row], pack to half2
#pragma unroll
    for (int mt = 0; mt < 2; mt++) {
        int rowA = row0 + warpM * 32 + mt * 16 + gid;
        int rowB = rowA + 8;
        float dA = (rowA < n) ? g_dinv[rowA] : 0.f;
        float dB = (rowB < n) ? g_dinv[rowB] : 0.f;
#pragma unroll
        for (int nt = 0; nt < 8; nt++) {
            int h2c = warpN * 32 + nt * 4 + tig;
            if (rowA < n) {
                __half2 p = __floats2half2_rn(acc[mt][nt][0] * dA, acc[mt][nt][1] * dA);
                g_h1h[(size_t)rowA * 64 + h2c] = *(uint32_t*)&p;
            }
            if (rowB < n) {
                __half2 p = __floats2half2_rn(acc[mt][nt][2] * dB, acc[mt][nt][3] * dB);
                g_h1h[(size_t)rowB * 64 + h2c] = *(uint32_t*)&p;
            }
        }
    }
}

// widen a half2 and accumulate into 2 floats
__device__ __forceinline__ void cvtadd(__half2 p, float& x, float& y) {
    float2 f = __half22float2(p);
    x += f.x; y += f.y;
}

// ------- agg1: unroll-4 + fp16 pair-sum; bias+relu+W2; resets g_cur/g_ctr -------
__global__ void __launch_bounds__(256) k_agg1(const float* __restrict__ b1,
                                              const float* __restrict__ W2, int n) {
    int gw = (blockIdx.x * blockDim.x + threadIdx.x) >> 5;
    int lane = threadIdx.x & 31;
    if (gw >= n) return;
    if (lane == 0) {
        g_cur[gw] = 0;
        if (gw == 0) { g_ctr[0] = 0; g_ctr[1] = 0; }
    }
    float dn = g_dinv[gw];
    const float2* h = (const float2*)g_h1h;   // 32 x 8B per row
    float a0x = 0.f, a0y = 0.f, a0z = 0.f, a0w = 0.f;
    float a1x = 0.f, a1y = 0.f, a1z = 0.f, a1w = 0.f;
    {   // self (pre-scaled by dinv in gemm epilogue)
        float2 sv = h[(size_t)gw * 32 + lane];
        cvtadd(*(__half2*)&sv.x, a0x, a0y);
        cvtadd(*(__half2*)&sv.y, a0z, a0w);
    }
    int e0 = g_off[gw], e1 = g_off[gw + 1];
    int e = e0;
    for (; e + 3 < e1; e += 4) {
        int s0 = g_csr[e], s1 = g_csr[e + 1], s2 = g_csr[e + 2], s3 = g_csr[e + 3];
        float2 v0 = h[(size_t)s0 * 32 + lane];
        float2 v1 = h[(size_t)s1 * 32 + lane];
        float2 v2 = h[(size_t)s2 * 32 + lane];
        float2 v3 = h[(size_t)s3 * 32 + lane];
        // pair-sum in fp16 (one extra rounding), then widen once
        __half2 pa = __hadd2(*(__half2*)&v0.x, *(__half2*)&v1.x);
        __half2 pb = __hadd2(*(__half2*)&v0.y, *(__half2*)&v1.y);
        __half2 qa = __hadd2(*(__half2*)&v2.x, *(__half2*)&v3.x);
        __half2 qb = __hadd2(*(__half2*)&v2.y, *(__half2*)&v3.y);
        cvtadd(pa, a0x, a0y);
        cvtadd(pb, a0z, a0w);
        cvtadd(qa, a1x, a1y);
        cvtadd(qb, a1z, a1w);
    }
    for (; e < e1; e++) {
        float2 v0 = h[(size_t)g_csr[e] * 32 + lane];
        cvtadd(*(__half2*)&v0.x, a1x, a1y);
        cvtadd(*(__half2*)&v0.y, a1z, a1w);
    }
    float4 b = ((const float4*)b1)[lane];
    float ax = fmaxf((a0x + a1x) * dn + b.x, 0.f);
    float ay = fmaxf((a0y + a1y) * dn + b.y, 0.f);
    float az = fmaxf((a0z + a1z) * dn + b.z, 0.f);
    float aw = fmaxf((a0w + a1w) * dn + b.w, 0.f);
    const float2* w2p = (const float2*)W2;
    float2 w0 = w2p[lane * 4 + 0], w1 = w2p[lane * 4 + 1];
    float2 w2v = w2p[lane * 4 + 2], w3 = w2p[lane * 4 + 3];
    float o0 = ax * w0.x + ay * w1.x + az * w2v.x + aw * w3.x;
    float o1 = ax * w0.y + ay * w1.y + az * w2v.y + aw * w3.y;
#pragma unroll
    for (int d = 16; d; d >>= 1) {
        o0 += __shfl_xor_sync(0xffffffffu, o0, d);
        o1 += __shfl_xor_sync(0xffffffffu, o1, d);
    }
    if (lane == 0) g_h2w[gw] = make_float2(o0 * dn, o1 * dn);  // pre-scale for L2
}

// ---------------- agg2: thread per node, unroll-4 ----------------
__global__ void k_agg2(const float* __restrict__ b2, float* __restrict__ out, int n) {
    int i = blockIdx.x * blockDim.x + threadIdx.x;
    if (i >= n) return;
    float dn = g_dinv[i];
    float2 hv = g_h2w[i];
    float p0 = hv.x, p1 = hv.y;                 // self (pre-scaled)
    float q0 = 0.f, q1 = 0.f;
    int e0 = g_off[i], e1 = g_off[i + 1];
    int e = e0;
    for (; e + 3 < e1; e += 4) {
        int s0 = g_csr[e], s1 = g_csr[e + 1], s2 = g_csr[e + 2], s3 = g_csr[e + 3];
        float2 v0 = g_h2w[s0], v1 = g_h2w[s1], v2 = g_h2w[s2], v3 = g_h2w[s3];
        p0 += v0.x; p1 += v0.y;
        q0 += v1.x; q1 += v1.y;
        p0 += v2.x; p1 += v2.y;
        q0 += v3.x; q1 += v3.y;
    }
    for (; e < e1; e++) {
        float2 v0 = g_h2w[g_csr[e]];
        p0 += v0.x; p1 += v0.y;
    }
    ((float2*)out)[i] = make_float2((p0 + q0) * dn + b2[0], (p1 + q1) * dn + b2[1]);
}

// ---------------- launch ----------------
extern "C" void kernel_launch(void* const* d_in, const int* in_sizes, int n_in,
                              void* d_out, int out_size) {
    const float* x  = (const float*)d_in[0];
    const void*  ei = d_in[1];
    const float* W1 = (const float*)d_in[2];
    const float* b1 = (const float*)d_in[3];
    const float* W2 = (const float*)d_in[4];
    const float* b2 = (const float*)d_in[5];
    float* out = (float*)d_out;

    const int n = in_sizes[0] / DD;       // 100000
    const int e = in_sizes[1] / 2;        // 600000

    cudaStream_t s2;
    cudaStreamCreateWithFlags(&s2, cudaStreamNonBlocking);
    cudaEvent_t ev1, ev2;
    cudaEventCreateWithFlags(&ev1, cudaEventDisableTiming);
    cudaEventCreateWithFlags(&ev2, cudaEventDisableTiming);

    k_deg<<<GB, GT>>>(ei, W1, n, e, GB);             // legacy stream
    cudaEventRecord(ev1, 0);
    cudaStreamWaitEvent(s2, ev1, 0);
    k_fill<<<(e + 255) / 256, 256, 0, s2>>>(ei, e, n);   // ∥ with gemm
    cudaEventRecord(ev2, s2);
    k_gemm1_tc<<<(n + 127) / 128, 256>>>(x, n);      // legacy, after k_deg
    cudaStreamWaitEvent(0, ev2, 0);                  // join: fill done
    k_agg1<<<(n + 7) / 8, 256>>>(b1, W2, n);
    k_agg2<<<(n + 255) / 256, 256>>>(b2, out, n);
}

// round 13
// speedup vs baseline: 1.0245x; 1.0245x over previous
#include <cuda_runtime.h>
#include <cuda_fp16.h>
#include <cstdint>

#define NN 100000
#define EE 600000
#define DD 128
#define GB 98            // k_deg grid (all blocks resident: 98 <= 148 SMs)
#define GT 1024          // k_deg block
#define SX 136           // smem row stride in words

// ---- device scratch (allocation-free rule: __device__ globals) ----
__device__ __align__(16) uint32_t g_h1h[(size_t)NN * 64]; // (x@W1)*dinv, fp16x2
__device__ __align__(16) float2 g_h2w[NN];               // layer-2 lin out * dinv
__device__ __align__(16) uint32_t g_w16[64 * DD];        // W1 packed half2 [k2][n]
__device__ int   g_cnt[NN];      // zeroed at end of each pass (k_deg phase2)
__device__ int   g_cur[NN];      // zeroed by k_agg1 each pass
__device__ int   g_off[NN + 1];
__device__ int   g_bsum[GB];
__device__ int   g_csr[EE];
__device__ float g_dinv[NN];
__device__ int   g_ctr[2];       // grid barriers; zeroed by k_agg1 each pass
__device__ int   g_is64;

// ---------------- grid barrier (all GB blocks resident) ----------------
__device__ __forceinline__ void gsync(int idx, int nb) {
    __syncthreads();
    if (threadIdx.x == 0) {
        __threadfence();
        atomicAdd(&g_ctr[idx], 1);
        while (((volatile int*)g_ctr)[idx] < nb) { }
        __threadfence();
    }
    __syncthreads();
}

// ============ k_deg: detect + count + wpack + scan + dinv ============
__global__ void __launch_bounds__(GT) k_deg(const void* __restrict__ ei,
                                            const float* __restrict__ W1,
                                            int n, int e, int nb) {
    __shared__ int s_is64;
    __shared__ int wsum[32];
    __shared__ int s_pre;
    int tid = threadIdx.x, lane = tid & 31, wid = tid >> 5;
    int b = blockIdx.x;
    int gstep = nb * GT;
    int gtid = b * GT + tid;

    if (tid == 0) {
        const unsigned* w = (const unsigned*)ei;
        int all0 = 1;
        for (int j = 1; j < 128; j += 2) all0 &= (w[j] == 0u);
        s_is64 = all0;
        if (b == 0) g_is64 = all0;
    }
    __syncthreads();
    int is64 = s_is64;

    // ---- phase0: degree count + W1 fp16 pack [k2][n] ----
    for (int i = gtid; i < e; i += gstep) {
        int t = is64 ? (int)((const long long*)ei)[(long long)e + i]
                     : ((const int*)ei)[e + i];
        if ((unsigned)t < (unsigned)n) atomicAdd(&g_cnt[t], 1);
    }
    for (int i = gtid; i < 64 * DD; i += gstep) {
        int k2 = i >> 7, nn = i & 127;
        __half2 p = __floats2half2_rn(W1[(2 * k2) * DD + nn],
                                      W1[(2 * k2 + 1) * DD + nn]);
        g_w16[i] = *(uint32_t*)&p;
    }
    gsync(0, nb);

    // ---- phase1: per-block exclusive scan of its 1024-count segment ----
    int i = b * GT + tid;
    int v = (i < n) ? g_cnt[i] : 0;
    int incl = v;
#pragma unroll
    for (int d = 1; d < 32; d <<= 1) {
        int y = __shfl_up_sync(0xffffffffu, incl, d);
        if (lane >= d) incl += y;
    }
    if (lane == 31) wsum[wid] = incl;
    __syncthreads();
    if (wid == 0) {
        int s = wsum[lane];
#pragma unroll
        for (int d = 1; d < 32; d <<= 1) {
            int y = __shfl_up_sync(0xffffffffu, s, d);
            if (lane >= d) s += y;
        }
        wsum[lane] = s;
    }
    __syncthreads();
    int wprev = wid ? wsum[wid - 1] : 0;
    int excl = wprev + incl - v;
    if (i < n) g_off[i] = excl;
    if (tid == GT - 1) g_bsum[b] = wprev + incl;
    gsync(1, nb);

    // ---- phase2: propagate block prefix; dinv; zero g_cnt for replay ----
    if (tid == 0) {
        int p = 0;
        for (int j = 0; j < b; j++) p += g_bsum[j];
        s_pre = p;
        if (b == nb - 1) g_off[n] = p + g_bsum[b];
    }
    __syncthreads();
    if (i < n) {
        g_off[i] += s_pre;
        g_dinv[i] = rsqrtf((float)(g_cnt[i] + 1));   // +1 = self-loop
        g_cnt[i] = 0;
    }
}

// ---------------- k_fill: CSR fill ----------------
__global__ void k_fill(const void* __restrict__ ei, int e, int n) {
    int i = blockIdx.x * blockDim.x + threadIdx.x;
    if (i >= e) return;
    int is64 = g_is64;
    int t = is64 ? (int)((const long long*)ei)[(long long)e + i]
                 : ((const int*)ei)[e + i];
    int s = is64 ? (int)((const long long*)ei)[i]
                 : ((const int*)ei)[i];
    if ((unsigned)t < (unsigned)n && (unsigned)s < (unsigned)n) {
        int p = atomicAdd(&g_cur[t], 1);
        g_csr[g_off[t] + p] = s;
    }
}

// ---------------- fp16 mma ----------------
__device__ __forceinline__ void mma16(float* c, const uint32_t* a, const uint32_t* b) {
    asm volatile(
        "mma.sync.aligned.m16n8k16.row.col.f32.f16.f16.f32 "
        "{%0,%1,%2,%3},{%4,%5,%6,%7},{%8,%9},{%0,%1,%2,%3};"
        : "+f"(c[0]), "+f"(c[1]), "+f"(c[2]), "+f"(c[3])
        : "r"(a[0]), "r"(a[1]), "r"(a[2]), "r"(a[3]), "r"(b[0]), "r"(b[1]));
}

// ------- GEMM1: fp16 MMA, fp32 accum; epilogue scales row by dinv[row] -------
__global__ void __launch_bounds__(256, 2)
k_gemm1_tc(const float* __restrict__ x, int n) {
    __shared__ uint32_t Xs[32 * SX];
    __shared__ uint32_t Ws[32 * SX];
    int tid = threadIdx.x;
    int wid = tid >> 5, lane = tid & 31;
    int gid = lane >> 2, tig = lane & 3;
    int warpM = wid & 3;
    int warpN = wid >> 2;
    int row0 = blockIdx.x * 128;

    float acc[2][8][4];
#pragma unroll
    for (int mt = 0; mt < 2; mt++)
#pragma unroll
        for (int nt = 0; nt < 8; nt++)
#pragma unroll
            for (int j = 0; j < 4; j++) acc[mt][nt][j] = 0.f;

    for (int c = 0; c < 2; c++) {
#pragma unroll
        for (int j = 0; j < 8; j++) {
            int idx = tid + j * 256;
            int r = idx >> 4, q = idx & 15;
            float4 v = make_float4(0.f, 0.f, 0.f, 0.f);
            if (row0 + r < n)
                v = *(const float4*)(x + (size_t)(row0 + r) * DD + c * 64 + q * 4);
            __half2 p0 = __floats2half2_rn(v.x, v.y);
            __half2 p1 = __floats2half2_rn(v.z, v.w);
            int rs = r ^ q;
            Xs[(2 * q) * SX + rs]     = *(uint32_t*)&p0;
            Xs[(2 * q + 1) * SX + rs] = *(uint32_t*)&p1;
        }
#pragma unroll
        for (int j = 0; j < 16; j++) {
            int idx = tid + j * 256;
            int k2 = idx >> 7, nn = idx & 127;
            uint32_t w = g_w16[(size_t)(c * 32 + k2) * DD + nn];
            Ws[k2 * SX + (nn ^ ((k2 >> 1) & 31))] = w;
        }
        __syncthreads();

#pragma unroll
        for (int ks = 0; ks < 4; ks++) {
            int m0 = ks * 4 + (tig >> 1);
            int m1 = m0 + 2;
            int k2a = ks * 8 + tig, k2b = k2a + 4;
            uint32_t a[2][4];
#pragma unroll
            for (int mt = 0; mt < 2; mt++) {
                int rb = warpM * 32 + mt * 16 + gid;
                a[mt][0] = Xs[k2a * SX + (rb ^ m0)];
                a[mt][1] = Xs[k2a * SX + ((rb + 8) ^ m0)];
                a[mt][2] = Xs[k2b * SX + (rb ^ m1)];
                a[mt][3] = Xs[k2b * SX + ((rb + 8) ^ m1)];
            }
#pragma unroll
            for (int nt = 0; nt < 8; nt++) {
                int nb = warpN * 64 + nt * 8 + gid;
                uint32_t b[2];
                b[0] = Ws[k2a * SX + (nb ^ m0)];
                b[1] = Ws[k2b * SX + (nb ^ m1)];
#pragma unroll
                for (int mt = 0; mt < 2; mt++)
                    mma16(acc[mt][nt], a[mt], b);
            }
        }
        __syncthreads();
    }

    // epilogue: scale by dinv[row], pack to half2
#pragma unroll
    for (int mt = 0; mt < 2; mt++) {
        int rowA = row0 + warpM * 32 + mt * 16 + gid;
        int rowB = rowA + 8;
        float dA = (rowA < n) ? g_dinv[rowA] : 0.f;
        float dB = (rowB < n) ? g_dinv[rowB] : 0.f;
#pragma unroll
        for (int nt = 0; nt < 8; nt++) {
            int h2c = warpN * 32 + nt * 4 + tig;
            if (rowA < n) {
                __half2 p = __floats2half2_rn(acc[mt][nt][0] * dA, acc[mt][nt][1] * dA);
                g_h1h[(size_t)rowA * 64 + h2c] = *(uint32_t*)&p;
            }
            if (rowB < n) {
                __half2 p = __floats2half2_rn(acc[mt][nt][2] * dB, acc[mt][nt][3] * dB);
                g_h1h[(size_t)rowB * 64 + h2c] = *(uint32_t*)&p;
            }
        }
    }
}

// widen a half2 and accumulate into 2 floats
__device__ __forceinline__ void cvtadd(__half2 p, float& x, float& y) {
    float2 f = __half22float2(p);
    x += f.x; y += f.y;
}

// ------- agg1: coalesced idx preload + shuffle; L1-bypass gathers -------
__global__ void __launch_bounds__(256) k_agg1(const float* __restrict__ b1,
                                              const float* __restrict__ W2, int n) {
    int gw = (blockIdx.x * blockDim.x + threadIdx.x) >> 5;
    int lane = threadIdx.x & 31;
    if (gw >= n) return;
    if (lane == 0) {
        g_cur[gw] = 0;
        if (gw == 0) { g_ctr[0] = 0; g_ctr[1] = 0; }
    }
    float dn = g_dinv[gw];
    const float2* h = (const float2*)g_h1h;   // 32 x 8B per row
    float a0x = 0.f, a0y = 0.f, a0z = 0.f, a0w = 0.f;
    float a1x = 0.f, a1y = 0.f, a1z = 0.f, a1w = 0.f;
    {   // self (pre-scaled by dinv in gemm epilogue)
        float2 sv = __ldcg(&h[(size_t)gw * 32 + lane]);
        cvtadd(*(__half2*)&sv.x, a0x, a0y);
        cvtadd(*(__half2*)&sv.y, a0z, a0w);
    }
    int e0 = g_off[gw], e1 = g_off[gw + 1];
    int deg = e1 - e0;
    // coalesced preload of up to 32 indices; broadcast via shuffle
    int myidx = (lane < deg) ? g_csr[e0 + lane] : 0;
    int full = deg < 32 ? deg : 32;
    int j = 0;
    for (; j + 3 < full; j += 4) {
        int s0 = __shfl_sync(0xffffffffu, myidx, j);
        int s1 = __shfl_sync(0xffffffffu, myidx, j + 1);
        int s2 = __shfl_sync(0xffffffffu, myidx, j + 2);
        int s3 = __shfl_sync(0xffffffffu, myidx, j + 3);
        float2 v0 = __ldcg(&h[(size_t)s0 * 32 + lane]);
        float2 v1 = __ldcg(&h[(size_t)s1 * 32 + lane]);
        float2 v2 = __ldcg(&h[(size_t)s2 * 32 + lane]);
        float2 v3 = __ldcg(&h[(size_t)s3 * 32 + lane]);
        __half2 pa = __hadd2(*(__half2*)&v0.x, *(__half2*)&v1.x);
        __half2 pb = __hadd2(*(__half2*)&v0.y, *(__half2*)&v1.y);
        __half2 qa = __hadd2(*(__half2*)&v2.x, *(__half2*)&v3.x);
        __half2 qb = __hadd2(*(__half2*)&v2.y, *(__half2*)&v3.y);
        cvtadd(pa, a0x, a0y);
        cvtadd(pb, a0z, a0w);
        cvtadd(qa, a1x, a1y);
        cvtadd(qb, a1z, a1w);
    }
    for (; j < full; j++) {
        int s = __shfl_sync(0xffffffffu, myidx, j);
        float2 v = __ldcg(&h[(size_t)s * 32 + lane]);
        cvtadd(*(__half2*)&v.x, a1x, a1y);
        cvtadd(*(__half2*)&v.y, a1z, a1w);
    }
    for (int e = e0 + 32; e < e1; e++) {      // deg>32 tail (practically never)
        int s = g_csr[e];
        float2 v = __ldcg(&h[(size_t)s * 32 + lane]);
        cvtadd(*(__half2*)&v.x, a1x, a1y);
        cvtadd(*(__half2*)&v.y, a1z, a1w);
    }
    float4 b = ((const float4*)b1)[lane];
    float ax = fmaxf((a0x + a1x) * dn + b.x, 0.f);
    float ay = fmaxf((a0y + a1y) * dn + b.y, 0.f);
    float az = fmaxf((a0z + a1z) * dn + b.z, 0.f);
    float aw = fmaxf((a0w + a1w) * dn + b.w, 0.f);
    const float2* w2p = (const float2*)W2;
    float2 w0 = w2p[lane * 4 + 0], w1 = w2p[lane * 4 + 1];
    float2 w2v = w2p[lane * 4 + 2], w3 = w2p[lane * 4 + 3];
    float o0 = ax * w0.x + ay * w1.x + az * w2v.x + aw * w3.x;
    float o1 = ax * w0.y + ay * w1.y + az * w2v.y + aw * w3.y;
#pragma unroll
    for (int d = 16; d; d >>= 1) {
        o0 += __shfl_xor_sync(0xffffffffu, o0, d);
        o1 += __shfl_xor_sync(0xffffffffu, o1, d);
    }
    if (lane == 0) g_h2w[gw] = make_float2(o0 * dn, o1 * dn);  // pre-scale for L2
}

// ---------------- agg2: thread per node, unroll-4 ----------------
__global__ void k_agg2(const float* __restrict__ b2, float* __restrict__ out, int n) {
    int i = blockIdx.x * blockDim.x + threadIdx.x;
    if (i >= n) return;
    float dn = g_dinv[i];
    float2 hv = g_h2w[i];
    float p0 = hv.x, p1 = hv.y;                 // self (pre-scaled)
    float q0 = 0.f, q1 = 0.f;
    int e0 = g_off[i], e1 = g_off[i + 1];
    int e = e0;
    for (; e + 3 < e1; e += 4) {
        int s0 = g_csr[e], s1 = g_csr[e + 1], s2 = g_csr[e + 2], s3 = g_csr[e + 3];
        float2 v0 = g_h2w[s0], v1 = g_h2w[s1], v2 = g_h2w[s2], v3 = g_h2w[s3];
        p0 += v0.x; p1 += v0.y;
        q0 += v1.x; q1 += v1.y;
        p0 += v2.x; p1 += v2.y;
        q0 += v3.x; q1 += v3.y;
    }
    for (; e < e1; e++) {
        float2 v0 = g_h2w[g_csr[e]];
        p0 += v0.x; p1 += v0.y;
    }
    ((float2*)out)[i] = make_float2((p0 + q0) * dn + b2[0], (p1 + q1) * dn + b2[1]);
}

// ---------------- launch (single stream) ----------------
extern "C" void kernel_launch(void* const* d_in, const int* in_sizes, int n_in,
                              void* d_out, int out_size) {
    const float* x  = (const float*)d_in[0];
    const void*  ei = d_in[1];
    const float* W1 = (const float*)d_in[2];
    const float* b1 = (const float*)d_in[3];
    const float* W2 = (const float*)d_in[4];
    const float* b2 = (const float*)d_in[5];
    float* out = (float*)d_out;

    const int n = in_sizes[0] / DD;       // 100000
    const int e = in_sizes[1] / 2;        // 600000

    k_deg<<<GB, GT>>>(ei, W1, n, e, GB);
    k_fill<<<(e + 255) / 256, 256>>>(ei, e, n);
    k_gemm1_tc<<<(n + 127) / 128, 256>>>(x, n);
    k_agg1<<<(n + 7) / 8, 256>>>(b1, W2, n);
    k_agg2<<<(n + 255) / 256, 256>>>(b2, out, n);
}

// round 14
// speedup vs baseline: 1.0978x; 1.0716x over previous
#include <cuda_runtime.h>
#include <cuda_fp16.h>
#include <cstdint>

#define NN 100000
#define EE 600000
#define DD 128
#define GB 98            // k_deg grid (all blocks resident: 98 <= 148 SMs)
#define GT 1024          // k_deg block
#define SX 136           // smem row stride in words
#define GEMM_SMEM (2 * 64 * SX * 4)   // Xs + Ws, bytes (69632)

// ---- device scratch (allocation-free rule: __device__ globals) ----
__device__ __align__(16) uint32_t g_h1h[(size_t)NN * 64]; // (x@W1)*dinv, fp16x2
__device__ __align__(16) float2 g_h2w[NN];               // layer-2 lin out * dinv
__device__ __align__(16) uint32_t g_w16[64 * DD];        // W1 packed half2 [k2][n]
__device__ int   g_cnt[NN];      // zeroed at end of each pass (k_deg phase2)
__device__ int   g_cur[NN];      // zeroed by k_agg1 each pass
__device__ int   g_off[NN + 1];
__device__ int   g_bsum[GB];
__device__ int   g_csr[EE];
__device__ float g_dinv[NN];
__device__ int   g_ctr[2];       // grid barriers; zeroed by k_agg1 each pass
__device__ int   g_is64;

// ---------------- grid barrier (all GB blocks resident) ----------------
__device__ __forceinline__ void gsync(int idx, int nb) {
    __syncthreads();
    if (threadIdx.x == 0) {
        __threadfence();
        atomicAdd(&g_ctr[idx], 1);
        while (((volatile int*)g_ctr)[idx] < nb) { }
        __threadfence();
    }
    __syncthreads();
}

// ============ k_deg: detect + count + wpack + scan + dinv ============
__global__ void __launch_bounds__(GT) k_deg(const void* __restrict__ ei,
                                            const float* __restrict__ W1,
                                            int n, int e, int nb) {
    __shared__ int s_is64;
    __shared__ int wsum[32];
    __shared__ int s_pre;
    int tid = threadIdx.x, lane = tid & 31, wid = tid >> 5;
    int b = blockIdx.x;
    int gstep = nb * GT;
    int gtid = b * GT + tid;

    if (tid == 0) {
        const unsigned* w = (const unsigned*)ei;
        int all0 = 1;
        for (int j = 1; j < 128; j += 2) all0 &= (w[j] == 0u);
        s_is64 = all0;
        if (b == 0) g_is64 = all0;
    }
    __syncthreads();
    int is64 = s_is64;

    // ---- phase0: degree count + W1 fp16 pack [k2][n] ----
    for (int i = gtid; i < e; i += gstep) {
        int t = is64 ? (int)((const long long*)ei)[(long long)e + i]
                     : ((const int*)ei)[e + i];
        if ((unsigned)t < (unsigned)n) atomicAdd(&g_cnt[t], 1);
    }
    for (int i = gtid; i < 64 * DD; i += gstep) {
        int k2 = i >> 7, nn = i & 127;
        __half2 p = __floats2half2_rn(W1[(2 * k2) * DD + nn],
                                      W1[(2 * k2 + 1) * DD + nn]);
        g_w16[i] = *(uint32_t*)&p;
    }
    gsync(0, nb);

    // ---- phase1: per-block exclusive scan of its 1024-count segment ----
    int i = b * GT + tid;
    int v = (i < n) ? g_cnt[i] : 0;
    int incl = v;
#pragma unroll
    for (int d = 1; d < 32; d <<= 1) {
        int y = __shfl_up_sync(0xffffffffu, incl, d);
        if (lane >= d) incl += y;
    }
    if (lane == 31) wsum[wid] = incl;
    __syncthreads();
    if (wid == 0) {
        int s = wsum[lane];
#pragma unroll
        for (int d = 1; d < 32; d <<= 1) {
            int y = __shfl_up_sync(0xffffffffu, s, d);
            if (lane >= d) s += y;
        }
        wsum[lane] = s;
    }
    __syncthreads();
    int wprev = wid ? wsum[wid - 1] : 0;
    int excl = wprev + incl - v;
    if (i < n) g_off[i] = excl;
    if (tid == GT - 1) g_bsum[b] = wprev + incl;
    gsync(1, nb);

    // ---- phase2: propagate block prefix; dinv; zero g_cnt for replay ----
    if (tid == 0) {
        int p = 0;
        for (int j = 0; j < b; j++) p += g_bsum[j];
        s_pre = p;
        if (b == nb - 1) g_off[n] = p + g_bsum[b];
    }
    __syncthreads();
    if (i < n) {
        g_off[i] += s_pre;
        g_dinv[i] = rsqrtf((float)(g_cnt[i] + 1));   // +1 = self-loop
        g_cnt[i] = 0;
    }
}

// ---------------- k_fill: CSR fill ----------------
__global__ void k_fill(const void* __restrict__ ei, int e, int n) {
    int i = blockIdx.x * blockDim.x + threadIdx.x;
    if (i >= e) return;
    int is64 = g_is64;
    int t = is64 ? (int)((const long long*)ei)[(long long)e + i]
                 : ((const int*)ei)[e + i];
    int s = is64 ? (int)((const long long*)ei)[i]
                 : ((const int*)ei)[i];
    if ((unsigned)t < (unsigned)n && (unsigned)s < (unsigned)n) {
        int p = atomicAdd(&g_cur[t], 1);
        g_csr[g_off[t] + p] = s;
    }
}

// ---------------- fp16 mma ----------------
__device__ __forceinline__ void mma16(float* c, const uint32_t* a, const uint32_t* b) {
    asm volatile(
        "mma.sync.aligned.m16n8k16.row.col.f32.f16.f16.f32 "
        "{%0,%1,%2,%3},{%4,%5,%6,%7},{%8,%9},{%0,%1,%2,%3};"
        : "+f"(c[0]), "+f"(c[1]), "+f"(c[2]), "+f"(c[3])
        : "r"(a[0]), "r"(a[1]), "r"(a[2]), "r"(a[3]), "r"(b[0]), "r"(b[1]));
}

// --- GEMM1: full-K in smem, ONE sync, fp16 MMA; epilogue scales by dinv ---
__global__ void __launch_bounds__(256, 2)
k_gemm1_tc(const float* __restrict__ x, int n) {
    extern __shared__ uint32_t smem[];
    uint32_t* Xs = smem;                 // 64 k2 x 128 rows (swizzled)
    uint32_t* Ws = smem + 64 * SX;       // 64 k2 x 128 cols (swizzled)
    int tid = threadIdx.x;
    int wid = tid >> 5, lane = tid & 31;
    int gid = lane >> 2, tig = lane & 3;
    int warpM = wid & 3;
    int warpN = wid >> 2;
    int row0 = blockIdx.x * 128;

    float acc[2][8][4];
#pragma unroll
    for (int mt = 0; mt < 2; mt++)
#pragma unroll
        for (int nt = 0; nt < 8; nt++)
#pragma unroll
            for (int j = 0; j < 4; j++) acc[mt][nt][j] = 0.f;

    // X: 128 rows x 32 float4 (full K=128), convert+swizzle into smem
#pragma unroll
    for (int j = 0; j < 16; j++) {
        int idx = tid + j * 256;          // 4096 float4
        int r = idx >> 5, q = idx & 31;   // q = k-quad (4 floats = 2 k2)
        float4 v = make_float4(0.f, 0.f, 0.f, 0.f);
        if (row0 + r < n)
            v = *(const float4*)(x + (size_t)(row0 + r) * DD + q * 4);
        __half2 p0 = __floats2half2_rn(v.x, v.y);
        __half2 p1 = __floats2half2_rn(v.z, v.w);
        int rs = r ^ q;
        Xs[(2 * q) * SX + rs]     = *(uint32_t*)&p0;
        Xs[(2 * q + 1) * SX + rs] = *(uint32_t*)&p1;
    }
    // W: 64 k2 x 128 n, copy+swizzle from packed g_w16
#pragma unroll
    for (int j = 0; j < 32; j++) {
        int idx = tid + j * 256;          // 8192 words
        int k2 = idx >> 7, nn = idx & 127;
        uint32_t w = g_w16[idx];
        Ws[k2 * SX + (nn ^ ((k2 >> 1) & 31))] = w;
    }
    __syncthreads();

#pragma unroll
    for (int ks = 0; ks < 8; ks++) {
        int m0 = ks * 4 + (tig >> 1);
        int m1 = m0 + 2;
        int k2a = ks * 8 + tig, k2b = k2a + 4;
        uint32_t a[2][4];
#pragma unroll
        for (int mt = 0; mt < 2; mt++) {
            int rb = warpM * 32 + mt * 16 + gid;
            a[mt][0] = Xs[k2a * SX + (rb ^ m0)];
            a[mt][1] = Xs[k2a * SX + ((rb + 8) ^ m0)];
            a[mt][2] = Xs[k2b * SX + (rb ^ m1)];
            a[mt][3] = Xs[k2b * SX + ((rb + 8) ^ m1)];
        }
#pragma unroll
        for (int nt = 0; nt < 8; nt++) {
            int nb = warpN * 64 + nt * 8 + gid;
            uint32_t b[2];
            b[0] = Ws[k2a * SX + (nb ^ m0)];
            b[1] = Ws[k2b * SX + (nb ^ m1)];
#pragma unroll
            for (int mt = 0; mt < 2; mt++)
                mma16(acc[mt][nt], a[mt], b);
        }
    }

    // epilogue: scale by dinv[row], pack to half2
#pragma unroll
    for (int mt = 0; mt < 2; mt++) {
        int rowA = row0 + warpM * 32 + mt * 16 + gid;
        int rowB = rowA + 8;
        float dA = (rowA < n) ? g_dinv[rowA] : 0.f;
        float dB = (rowB < n) ? g_dinv[rowB] : 0.f;
#pragma unroll
        for (int nt = 0; nt < 8; nt++) {
            int h2c = warpN * 32 + nt * 4 + tig;
            if (rowA < n) {
                __half2 p = __floats2half2_rn(acc[mt][nt][0] * dA, acc[mt][nt][1] * dA);
                g_h1h[(size_t)rowA * 64 + h2c] = *(uint32_t*)&p;
            }
            if (rowB < n) {
                __half2 p = __floats2half2_rn(acc[mt][nt][2] * dB, acc[mt][nt][3] * dB);
                g_h1h[(size_t)rowB * 64 + h2c] = *(uint32_t*)&p;
            }
        }
    }
}

// widen a half2 and accumulate into 2 floats
__device__ __forceinline__ void cvtadd(__half2 p, float& x, float& y) {
    float2 f = __half22float2(p);
    x += f.x; y += f.y;
}

// ------- agg1: coalesced idx preload + shuffle; L1-bypass gathers -------
__global__ void __launch_bounds__(256) k_agg1(const float* __restrict__ b1,
                                              const float* __restrict__ W2, int n) {
    int gw = (blockIdx.x * blockDim.x + threadIdx.x) >> 5;
    int lane = threadIdx.x & 31;
    if (gw >= n) return;
    if (lane == 0) {
        g_cur[gw] = 0;
        if (gw == 0) { g_ctr[0] = 0; g_ctr[1] = 0; }
    }
    float dn = g_dinv[gw];
    const float2* h = (const float2*)g_h1h;   // 32 x 8B per row
    float a0x = 0.f, a0y = 0.f, a0z = 0.f, a0w = 0.f;
    float a1x = 0.f, a1y = 0.f, a1z = 0.f, a1w = 0.f;
    {   // self (pre-scaled by dinv in gemm epilogue)
        float2 sv = __ldcg(&h[(size_t)gw * 32 + lane]);
        cvtadd(*(__half2*)&sv.x, a0x, a0y);
        cvtadd(*(__half2*)&sv.y, a0z, a0w);
    }
    int e0 = g_off[gw], e1 = g_off[gw + 1];
    int deg = e1 - e0;
    int myidx = (lane < deg) ? g_csr[e0 + lane] : 0;
    int full = deg < 32 ? deg : 32;
    int j = 0;
    for (; j + 3 < full; j += 4) {
        int s0 = __shfl_sync(0xffffffffu, myidx, j);
        int s1 = __shfl_sync(0xffffffffu, myidx, j + 1);
        int s2 = __shfl_sync(0xffffffffu, myidx, j + 2);
        int s3 = __shfl_sync(0xffffffffu, myidx, j + 3);
        float2 v0 = __ldcg(&h[(size_t)s0 * 32 + lane]);
        float2 v1 = __ldcg(&h[(size_t)s1 * 32 + lane]);
        float2 v2 = __ldcg(&h[(size_t)s2 * 32 + lane]);
        float2 v3 = __ldcg(&h[(size_t)s3 * 32 + lane]);
        __half2 pa = __hadd2(*(__half2*)&v0.x, *(__half2*)&v1.x);
        __half2 pb = __hadd2(*(__half2*)&v0.y, *(__half2*)&v1.y);
        __half2 qa = __hadd2(*(__half2*)&v2.x, *(__half2*)&v3.x);
        __half2 qb = __hadd2(*(__half2*)&v2.y, *(__half2*)&v3.y);
        cvtadd(pa, a0x, a0y);
        cvtadd(pb, a0z, a0w);
        cvtadd(qa, a1x, a1y);
        cvtadd(qb, a1z, a1w);
    }
    for (; j < full; j++) {
        int s = __shfl_sync(0xffffffffu, myidx, j);
        float2 v = __ldcg(&h[(size_t)s * 32 + lane]);
        cvtadd(*(__half2*)&v.x, a1x, a1y);
        cvtadd(*(__half2*)&v.y, a1z, a1w);
    }
    for (int e = e0 + 32; e < e1; e++) {      // deg>32 tail (practically never)
        int s = g_csr[e];
        float2 v = __ldcg(&h[(size_t)s * 32 + lane]);
        cvtadd(*(__half2*)&v.x, a1x, a1y);
        cvtadd(*(__half2*)&v.y, a1z, a1w);
    }
    float4 b = ((const float4*)b1)[lane];
    float ax = fmaxf((a0x + a1x) * dn + b.x, 0.f);
    float ay = fmaxf((a0y + a1y) * dn + b.y, 0.f);
    float az = fmaxf((a0z + a1z) * dn + b.z, 0.f);
    float aw = fmaxf((a0w + a1w) * dn + b.w, 0.f);
    const float2* w2p = (const float2*)W2;
    float2 w0 = w2p[lane * 4 + 0], w1 = w2p[lane * 4 + 1];
    float2 w2v = w2p[lane * 4 + 2], w3 = w2p[lane * 4 + 3];
    float o0 = ax * w0.x + ay * w1.x + az * w2v.x + aw * w3.x;
    float o1 = ax * w0.y + ay * w1.y + az * w2v.y + aw * w3.y;
#pragma unroll
    for (int d = 16; d; d >>= 1) {
        o0 += __shfl_xor_sync(0xffffffffu, o0, d);
        o1 += __shfl_xor_sync(0xffffffffu, o1, d);
    }
    if (lane == 0) g_h2w[gw] = make_float2(o0 * dn, o1 * dn);  // pre-scale for L2
}

// ---------------- agg2: thread per node, unroll-4 ----------------
__global__ void k_agg2(const float* __restrict__ b2, float* __restrict__ out, int n) {
    int i = blockIdx.x * blockDim.x + threadIdx.x;
    if (i >= n) return;
    float dn = g_dinv[i];
    float2 hv = g_h2w[i];
    float p0 = hv.x, p1 = hv.y;                 // self (pre-scaled)
    float q0 = 0.f, q1 = 0.f;
    int e0 = g_off[i], e1 = g_off[i + 1];
    int e = e0;
    for (; e + 3 < e1; e += 4) {
        int s0 = g_csr[e], s1 = g_csr[e + 1], s2 = g_csr[e + 2], s3 = g_csr[e + 3];
        float2 v0 = g_h2w[s0], v1 = g_h2w[s1], v2 = g_h2w[s2], v3 = g_h2w[s3];
        p0 += v0.x; p1 += v0.y;
        q0 += v1.x; q1 += v1.y;
        p0 += v2.x; p1 += v2.y;
        q0 += v3.x; q1 += v3.y;
    }
    for (; e < e1; e++) {
        float2 v0 = g_h2w[g_csr[e]];
        p0 += v0.x; p1 += v0.y;
    }
    ((float2*)out)[i] = make_float2((p0 + q0) * dn + b2[0], (p1 + q1) * dn + b2[1]);
}

// ---------------- launch (single stream) ----------------
extern "C" void kernel_launch(void* const* d_in, const int* in_sizes, int n_in,
                              void* d_out, int out_size) {
    const float* x  = (const float*)d_in[0];
    const void*  ei = d_in[1];
    const float* W1 = (const float*)d_in[2];
    const float* b1 = (const float*)d_in[3];
    const float* W2 = (const float*)d_in[4];
    const float* b2 = (const float*)d_in[5];
    float* out = (float*)d_out;

    const int n = in_sizes[0] / DD;       // 100000
    const int e = in_sizes[1] / 2;        // 600000

    cudaFuncSetAttribute(k_gemm1_tc,
                         cudaFuncAttributeMaxDynamicSharedMemorySize, GEMM_SMEM);

    k_deg<<<GB, GT>>>(ei, W1, n, e, GB);
    k_fill<<<(e + 255) / 256, 256>>>(ei, e, n);
    k_gemm1_tc<<<(n + 127) / 128, 256, GEMM_SMEM>>>(x, n);
    k_agg1<<<(n + 7) / 8, 256>>>(b1, W2, n);
    k_agg2<<<(n + 255) / 256, 256>>>(b2, out, n);
}